// round 16
// baseline (speedup 1.0000x reference)
#include <cuda_runtime.h>
#include <cuda_fp16.h>
#include <cstdint>

// ---------------- problem constants ----------------
#define N_TOK   16384          // B*S
#define D_DIM   256
#define K_SUB   3686
#define K_PAD   3712           // 29 * 128
#define N_YT    29             // candidate tiles of 128
#define NGRP    928            // 29 * 32 groups of 4 candidates
#define OUT_TOKENS  (N_TOK * D_DIM)
#define OUT_LOSS    OUT_TOKENS
#define OUT_IDX     (OUT_TOKENS + 1)

// ---------------- device scratch ----------------
__device__ __align__(16) __half g_xh[N_TOK * D_DIM];      // x hi fp16   8.4 MB
__device__ __align__(16) __half g_ch[K_PAD * D_DIM];      // c hi fp16   1.9 MB
__device__ __align__(16) __half g_gmin[(size_t)N_TOK * NGRP]; // group mins, 30.4 MB
__device__ float g_tmin[N_TOK * 32];                      // per-(tok,tile) exact min
__device__ float g_c2[K_PAD];
__device__ float g_nxh[N_TOK];                            // ||xh||
__device__ float g_nxl[N_TOK];                            // ||x - xh||
__device__ unsigned g_mcl;                                // max_k ||cl|| bits
__device__ unsigned g_mc;                                 // max_k ||c||  bits
__device__ float g_tokloss[N_TOK];

// ---------------- PTX helpers ----------------
__device__ __forceinline__ uint32_t smem_u32(const void* p) {
    uint32_t a;
    asm("{ .reg .u64 t; cvta.to.shared.u64 t, %1; cvt.u32.u64 %0, t; }" : "=r"(a) : "l"(p));
    return a;
}
__device__ __forceinline__ void cpa16(uint32_t dst, const void* src) {
    asm volatile("cp.async.cg.shared.global [%0], [%1], 16;" :: "r"(dst), "l"(src));
}
#define CP_COMMIT() asm volatile("cp.async.commit_group;" ::: "memory")
#define CP_WAIT(n)  asm volatile("cp.async.wait_group %0;" :: "n"(n) : "memory")

__device__ __forceinline__ void ldsm4(uint32_t* r, uint32_t a) {
    asm volatile("ldmatrix.sync.aligned.m8n8.x4.shared.b16 {%0,%1,%2,%3}, [%4];"
        : "=r"(r[0]), "=r"(r[1]), "=r"(r[2]), "=r"(r[3]) : "r"(a));
}
__device__ __forceinline__ void mma16816(float* c, const uint32_t* a,
                                         uint32_t b0, uint32_t b1) {
    asm volatile("mma.sync.aligned.m16n8k16.row.col.f32.f16.f16.f32 "
        "{%0,%1,%2,%3}, {%4,%5,%6,%7}, {%8,%9}, {%0,%1,%2,%3};"
        : "+f"(c[0]), "+f"(c[1]), "+f"(c[2]), "+f"(c[3])
        : "r"(a[0]), "r"(a[1]), "r"(a[2]), "r"(a[3]), "r"(b0), "r"(b1));
}

// ---------------- kernel 1a: x -> xh fp16; exact norms ----
__global__ void k_prep_x(const float* __restrict__ x) {
    int wid = threadIdx.x >> 5, lane = threadIdx.x & 31;
    int tok = blockIdx.x * 8 + wid;
    const float* xr = x + (size_t)tok * D_DIM + lane * 8;
    float4 a = ((const float4*)xr)[0];
    float4 b = ((const float4*)xr)[1];
    float v[8] = {a.x, a.y, a.z, a.w, b.x, b.y, b.z, b.w};
    __half h[8];
    float sh = 0.f, sl = 0.f;
    #pragma unroll
    for (int i = 0; i < 8; i++) {
        h[i] = __float2half_rn(v[i]);
        float hf = __half2float(h[i]);
        float lf = v[i] - hf;
        sh += hf * hf; sl += lf * lf;
    }
    *(uint4*)(g_xh + (size_t)tok * D_DIM + lane * 8) = *(uint4*)h;
    #pragma unroll
    for (int o = 16; o; o >>= 1) {
        sh += __shfl_xor_sync(0xffffffffu, sh, o);
        sl += __shfl_xor_sync(0xffffffffu, sl, o);
    }
    if (lane == 0) {
        g_nxh[tok] = sqrtf(sh);
        g_nxl[tok] = sqrtf(sl);
    }
}

// ---- kernel 1b: gather sub-codebook -> ch fp16; c2; global max norms ----
__global__ void k_prep_c(const float* __restrict__ cb, const int* __restrict__ rnd) {
    int k = blockIdx.x;          // 0..K_PAD-1
    int t = threadIdx.x;         // 64 threads x float4
    __shared__ float s2w[2], slw[2];
    float4 v = make_float4(0.f, 0.f, 0.f, 0.f);
    if (k < K_SUB) v = ((const float4*)(cb + (size_t)rnd[k] * D_DIM))[t];
    __half h[4] = {__float2half_rn(v.x), __float2half_rn(v.y),
                   __float2half_rn(v.z), __float2half_rn(v.w)};
    *(uint2*)(g_ch + (size_t)k * D_DIM + t * 4) = *(uint2*)h;
    float lx = v.x - __half2float(h[0]), ly = v.y - __half2float(h[1]);
    float lz = v.z - __half2float(h[2]), lw = v.w - __half2float(h[3]);
    float s2 = v.x*v.x + v.y*v.y + v.z*v.z + v.w*v.w;
    float sl = lx*lx + ly*ly + lz*lz + lw*lw;
    #pragma unroll
    for (int o = 16; o; o >>= 1) {
        s2 += __shfl_down_sync(0xffffffffu, s2, o);
        sl += __shfl_down_sync(0xffffffffu, sl, o);
    }
    if ((t & 31) == 0) { s2w[t >> 5] = s2; slw[t >> 5] = sl; }
    __syncthreads();
    if (t == 0) {
        float c2 = s2w[0] + s2w[1];
        float cl2 = slw[0] + slw[1];
        g_c2[k] = (k < K_SUB) ? c2 : 3.0e38f;
        if (k < K_SUB) {
            atomicMax(&g_mc,  __float_as_uint(sqrtf(c2)));
            atomicMax(&g_mcl, __float_as_uint(sqrtf(cl2)));
        }
    }
}

// --- kernel 2: PERSISTENT fp16 HMMA GEMM (A resident; B ring over 29 tiles) ---
// grid = 128 CTAs (1/SM), 256 threads, warp grid 2(m)x4(n), warp tile 64x32.
// A: 4 chunk-tiles x 16 KB resident. B: 3-stage x 16 KB cp.async ring,
// flat loop cc = tile*4 + ch over 116 chunks. Per-tile epilogue: exact fp32
// tile min + rd-rounded fp16 group-of-4 mins.
#define A_TOT  65536                  // 4 x 16 KB resident A
#define B_ST   16384
#define DYN_SMEM (A_TOT + 3 * B_ST + 1024)   // ~113 KB
#define N_CHUNK (N_YT * 4)            // 116

__global__ void __launch_bounds__(256, 1) k_tc(void) {
    extern __shared__ __align__(16) unsigned char dynraw[];
    char* sb = (char*)(((uintptr_t)dynraw + 1023) & ~(uintptr_t)1023);
    const uint32_t s0 = smem_u32(sb);

    __shared__ float c2s[2][128];
    __shared__ float sd[128][4];
    __shared__ __align__(16) __half sd2[128][32];

    const int tid = threadIdx.x;
    const int wid = tid >> 5, lane = tid & 31;
    const int wm = wid & 1, wn = wid >> 1;
    const int lr = lane & 7, lg = lane >> 3;
    const int tokBase = blockIdx.x * 128;

    const __half* Ag = g_xh + (size_t)tokBase * D_DIM;

    // resident A: 4 chunk-tiles, 16 float4 per thread total
    #pragma unroll
    for (int ch = 0; ch < 4; ch++) {
        #pragma unroll
        for (int q = 0; q < 4; q++) {
            int idx = q * 256 + tid;
            int row = idx >> 3, c = idx & 7;
            cpa16(s0 + ch * B_ST + row * 128 + ((c ^ (row & 7)) << 4),
                  Ag + (size_t)row * D_DIM + ch * 64 + c * 8);
        }
    }
    CP_COMMIT();                      // group: A

    auto issueB = [&](int cc) {
        int tile = cc >> 2, ch = cc & 3;
        const uint32_t st = s0 + A_TOT + (cc % 3) * B_ST;
        const __half* Bg = g_ch + (size_t)(tile * 128) * D_DIM;
        #pragma unroll
        for (int q = 0; q < 4; q++) {
            int idx = q * 256 + tid;
            int row = idx >> 3, c = idx & 7;
            cpa16(st + row * 128 + ((c ^ (row & 7)) << 4),
                  Bg + (size_t)row * D_DIM + ch * 64 + c * 8);
        }
        CP_COMMIT();
    };

    issueB(0);
    issueB(1);
    if (tid < 128) c2s[0][tid] = g_c2[tid];

    float acc[4][4][4];
    #pragma unroll
    for (int a = 0; a < 4; a++)
        #pragma unroll
        for (int b = 0; b < 4; b++)
            #pragma unroll
            for (int e = 0; e < 4; e++) acc[a][b][e] = 0.f;

    int arow[4], brow[2];
    #pragma unroll
    for (int mf = 0; mf < 4; mf++) arow[mf] = wm * 64 + mf * 16 + lr + ((lg & 1) << 3);
    #pragma unroll
    for (int nb = 0; nb < 2; nb++) brow[nb] = wn * 32 + nb * 16 + lr + ((lg >> 1) << 3);
    const int acol = lg >> 1, bcol = lg & 1;

    #pragma unroll 1
    for (int cc = 0; cc < N_CHUNK; ++cc) {
        const int tile = cc >> 2, ch = cc & 3;
        if (cc < N_CHUNK - 1) { CP_WAIT(1); } else { CP_WAIT(0); }
        __syncthreads();              // chunk cc resident; sd2 of prior tile free
        if (cc + 2 < N_CHUNK) issueB(cc + 2);
        if (ch == 0 && tile + 1 < N_YT && tid < 128)
            c2s[(tile + 1) & 1][tid] = g_c2[(tile + 1) * 128 + tid];

        const uint32_t sA = s0 + ch * B_ST;              // resident A chunk-tile
        const uint32_t sB = s0 + A_TOT + (cc % 3) * B_ST;
        #pragma unroll
        for (int ks = 0; ks < 4; ++ks) {
            uint32_t af[4][4], bf[2][4];
            #pragma unroll
            for (int mf = 0; mf < 4; mf++) {
                int r = arow[mf], c16 = ks * 2 + acol;
                ldsm4(af[mf], sA + r * 128 + ((c16 ^ (r & 7)) << 4));
            }
            #pragma unroll
            for (int nb = 0; nb < 2; nb++) {
                int r = brow[nb], c16 = ks * 2 + bcol;
                ldsm4(bf[nb], sB + r * 128 + ((c16 ^ (r & 7)) << 4));
            }
            #pragma unroll
            for (int mf = 0; mf < 4; mf++)
                #pragma unroll
                for (int nf = 0; nf < 4; nf++)
                    mma16816(acc[mf][nf], af[mf], bf[nf >> 1][(nf & 1) * 2],
                             bf[nf >> 1][(nf & 1) * 2 + 1]);
        }

        if (ch == 3) {
            // epilogue for this tile: group-of-4 mins (rd) + exact tile min
            const float* c2p = c2s[tile & 1];
            #pragma unroll
            for (int mf = 0; mf < 4; mf++) {
                #pragma unroll
                for (int h = 0; h < 2; h++) {
                    int rowL = wm * 64 + mf * 16 + (lane >> 2) + h * 8;
                    float best = 3.4e38f;
                    #pragma unroll
                    for (int nf = 0; nf < 4; nf++) {
                        int colL = wn * 32 + nf * 8 + (lane & 3) * 2;
                        float d0 = c2p[colL]     - 2.0f * acc[mf][nf][h * 2];
                        float d1 = c2p[colL + 1] - 2.0f * acc[mf][nf][h * 2 + 1];
                        float m2 = fminf(d0, d1);
                        float mq = fminf(m2, __shfl_xor_sync(0xffffffffu, m2, 1));
                        if (((lane & 3) & 1) == 0)
                            sd2[rowL][wn * 8 + nf * 2 + ((lane & 3) >> 1)] =
                                __float2half_rd(mq);
                        best = fminf(best, fminf(mq, __shfl_xor_sync(0xffffffffu, mq, 2)));
                    }
                    if ((lane & 3) == 0) sd[rowL][wn] = best;
                }
            }
            __syncthreads();
            if (tid < 128) {
                float tmin = fminf(fminf(sd[tid][0], sd[tid][1]),
                                   fminf(sd[tid][2], sd[tid][3]));
                g_tmin[(tokBase + tid) * 32 + tile] = tmin;
                const uint4* s = (const uint4*)&sd2[tid][0];
                uint4* d = (uint4*)(g_gmin + (size_t)(tokBase + tid) * NGRP + tile * 32);
                d[0] = s[0]; d[1] = s[1]; d[2] = s[2]; d[3] = s[3];
            }
            // acc reset for next tile
            #pragma unroll
            for (int a = 0; a < 4; a++)
                #pragma unroll
                for (int b = 0; b < 4; b++)
                    #pragma unroll
                    for (int e = 0; e < 4; e++) acc[a][b][e] = 0.f;
            // sd2/sd reuse protected by the next iteration's __syncthreads
        }
    }
}

// ------- kernel 3: rescue + exact argmin + fused gather + loss partial -------
__global__ void k_rescue(const float* __restrict__ x, const float* __restrict__ cb,
                         const int* __restrict__ rnd, float* __restrict__ out) {
    int wid = threadIdx.x >> 5, lane = threadIdx.x & 31;
    int tok = blockIdx.x * 8 + wid;

    float tm = (lane < N_YT) ? g_tmin[tok * 32 + lane] : 3.4e38f;
    float dmin = tm;
    #pragma unroll
    for (int o = 16; o; o >>= 1)
        dmin = fminf(dmin, __shfl_xor_sync(0xffffffffu, dmin, o));

    float MCL = __uint_as_float(g_mcl), MC = __uint_as_float(g_mc);
    float B = 2.0f * (g_nxh[tok] * MCL + g_nxl[tok] * MC);
    float thr = dmin + 2.0f * B + 0.01f;
    unsigned tmask = __ballot_sync(0xffffffffu, tm <= thr);

    const float* xr = x + (size_t)tok * D_DIM + lane * 8;
    float4 xa = ((const float4*)xr)[0];
    float4 xb = ((const float4*)xr)[1];

    float best = 3.4e38f; int bi = 0x7fffffff;
    auto exact = [&](int kk) {
        const float* cr = cb + (size_t)rnd[kk] * D_DIM + lane * 8;
        float4 ca = ((const float4*)cr)[0];
        float4 cv = ((const float4*)cr)[1];
        float p = xa.x*ca.x + xa.y*ca.y + xa.z*ca.z + xa.w*ca.w
                + xb.x*cv.x + xb.y*cv.y + xb.z*cv.z + xb.w*cv.w;
        #pragma unroll
        for (int o = 16; o; o >>= 1) p += __shfl_xor_sync(0xffffffffu, p, o);
        float dex = g_c2[kk] - 2.0f * p;
        if (dex < best || (dex == best && kk < bi)) { best = dex; bi = kk; }
    };

    const __half* grow = g_gmin + (size_t)tok * NGRP;
    while (tmask) {
        int t = __ffs(tmask) - 1; tmask &= tmask - 1;
        float gm = __half2float(grow[t * 32 + lane]);
        unsigned gmask = __ballot_sync(0xffffffffu, gm <= thr);
        while (gmask) {
            int g = __ffs(gmask) - 1; gmask &= gmask - 1;
            int kb = t * 128 + g * 4;
            exact(kb); exact(kb + 1); exact(kb + 2); exact(kb + 3);
        }
    }

    // fused gather + per-token loss
    int ci = rnd[bi];
    const float4* crow = (const float4*)(cb + (size_t)ci * D_DIM);
    float4 c0 = crow[lane * 2], c1 = crow[lane * 2 + 1];
    float4* orow = (float4*)(out + (size_t)tok * D_DIM);
    orow[lane * 2] = c0; orow[lane * 2 + 1] = c1;
    float dx, s = 0.f;
    dx = c0.x - xa.x; s += dx * dx;  dx = c0.y - xa.y; s += dx * dx;
    dx = c0.z - xa.z; s += dx * dx;  dx = c0.w - xa.w; s += dx * dx;
    dx = c1.x - xb.x; s += dx * dx;  dx = c1.y - xb.y; s += dx * dx;
    dx = c1.z - xb.z; s += dx * dx;  dx = c1.w - xb.w; s += dx * dx;
    #pragma unroll
    for (int o = 16; o; o >>= 1) s += __shfl_xor_sync(0xffffffffu, s, o);
    if (lane == 0) {
        g_tokloss[tok] = s;
        out[OUT_IDX + tok] = (float)ci;
    }
}

// ---------------- kernel 4: deterministic loss reduce ----------------
__global__ void k_loss(float* __restrict__ out) {
    __shared__ float red[1024];
    int tid = threadIdx.x;
    float s = 0.f;
    for (int j = tid; j < N_TOK; j += 1024) s += g_tokloss[j];
    red[tid] = s;
    __syncthreads();
    for (int o = 512; o; o >>= 1) {
        if (tid < o) red[tid] += red[tid + o];
        __syncthreads();
    }
    if (tid == 0) out[OUT_LOSS] = red[0] / (float)OUT_TOKENS;
}

// ---------------- launch ----------------
extern "C" void kernel_launch(void* const* d_in, const int* in_sizes, int n_in,
                              void* d_out, int out_size) {
    const float* x   = (const float*)d_in[0];
    const float* cb  = (const float*)d_in[1];
    const int*   rnd = (const int*)d_in[2];
    float* out = (float*)d_out;

    static int smem_set = 0;
    if (!smem_set) {
        cudaFuncSetAttribute(k_tc, cudaFuncAttributeMaxDynamicSharedMemorySize, DYN_SMEM);
        smem_set = 1;
    }

    k_prep_x<<<2048, 256>>>(x);
    k_prep_c<<<K_PAD, 64>>>(cb, rnd);
    k_tc<<<128, 256, DYN_SMEM>>>();
    k_rescue<<<2048, 256>>>(x, cb, rnd, out);
    k_loss<<<1, 1024>>>(out);
}

// round 17
// speedup vs baseline: 1.2276x; 1.2276x over previous
#include <cuda_runtime.h>
#include <cuda_fp16.h>
#include <cstdint>

// ---------------- problem constants ----------------
#define N_TOK   16384          // B*S
#define D_DIM   256
#define K_SUB   3686
#define K_PAD   3712           // 29 * 128
#define N_YT    29             // candidate tiles of 128
#define NGRP    928            // 29 * 32 groups of 4 candidates
#define OUT_TOKENS  (N_TOK * D_DIM)
#define OUT_LOSS    OUT_TOKENS
#define OUT_IDX     (OUT_TOKENS + 1)

// ---------------- device scratch ----------------
__device__ __align__(16) __half g_xh[N_TOK * D_DIM];      // x hi fp16   8.4 MB
__device__ __align__(16) __half g_ch[K_PAD * D_DIM];      // c hi fp16   1.9 MB
__device__ __align__(16) __half g_gmin[(size_t)N_TOK * NGRP]; // group mins, 30.4 MB
__device__ float g_tmin[N_TOK * 32];                      // per-(tok,tile) exact min
__device__ float g_c2[K_PAD];
__device__ float g_nxh[N_TOK];                            // ||xh||
__device__ float g_nxl[N_TOK];                            // ||x - xh||
__device__ unsigned g_mcl;                                // max_k ||cl|| bits
__device__ unsigned g_mc;                                 // max_k ||c||  bits
__device__ float g_tokloss[N_TOK];

// ---------------- PTX helpers ----------------
__device__ __forceinline__ uint32_t smem_u32(const void* p) {
    uint32_t a;
    asm("{ .reg .u64 t; cvta.to.shared.u64 t, %1; cvt.u32.u64 %0, t; }" : "=r"(a) : "l"(p));
    return a;
}
__device__ __forceinline__ void cpa16(uint32_t dst, const void* src) {
    asm volatile("cp.async.cg.shared.global [%0], [%1], 16;" :: "r"(dst), "l"(src));
}
#define CP_COMMIT() asm volatile("cp.async.commit_group;" ::: "memory")
#define CP_WAIT(n)  asm volatile("cp.async.wait_group %0;" :: "n"(n) : "memory")

__device__ __forceinline__ void ldsm4(uint32_t* r, uint32_t a) {
    asm volatile("ldmatrix.sync.aligned.m8n8.x4.shared.b16 {%0,%1,%2,%3}, [%4];"
        : "=r"(r[0]), "=r"(r[1]), "=r"(r[2]), "=r"(r[3]) : "r"(a));
}
__device__ __forceinline__ void mma16816(float* c, const uint32_t* a,
                                         uint32_t b0, uint32_t b1) {
    asm volatile("mma.sync.aligned.m16n8k16.row.col.f32.f16.f16.f32 "
        "{%0,%1,%2,%3}, {%4,%5,%6,%7}, {%8,%9}, {%0,%1,%2,%3};"
        : "+f"(c[0]), "+f"(c[1]), "+f"(c[2]), "+f"(c[3])
        : "r"(a[0]), "r"(a[1]), "r"(a[2]), "r"(a[3]), "r"(b0), "r"(b1));
}

// ---------------- kernel 1: fused prep (x split + codebook gather) ----------
// blocks [0,2048): x -> xh fp16, exact norms (warp per token, 8 tokens/block)
// blocks [2048,2976): 4 codebook rows per block, 64 threads per row
__global__ void k_prep(const float* __restrict__ x, const float* __restrict__ cb,
                       const int* __restrict__ rnd) {
    if (blockIdx.x < 2048) {
        int wid = threadIdx.x >> 5, lane = threadIdx.x & 31;
        int tok = blockIdx.x * 8 + wid;
        const float* xr = x + (size_t)tok * D_DIM + lane * 8;
        float4 a = ((const float4*)xr)[0];
        float4 b = ((const float4*)xr)[1];
        float v[8] = {a.x, a.y, a.z, a.w, b.x, b.y, b.z, b.w};
        __half h[8];
        float sh = 0.f, sl = 0.f;
        #pragma unroll
        for (int i = 0; i < 8; i++) {
            h[i] = __float2half_rn(v[i]);
            float hf = __half2float(h[i]);
            float lf = v[i] - hf;
            sh += hf * hf; sl += lf * lf;
        }
        *(uint4*)(g_xh + (size_t)tok * D_DIM + lane * 8) = *(uint4*)h;
        #pragma unroll
        for (int o = 16; o; o >>= 1) {
            sh += __shfl_xor_sync(0xffffffffu, sh, o);
            sl += __shfl_xor_sync(0xffffffffu, sl, o);
        }
        if (lane == 0) {
            g_nxh[tok] = sqrtf(sh);
            g_nxl[tok] = sqrtf(sl);
        }
    } else {
        __shared__ float s2w[4][2], slw[4][2];
        int g = threadIdx.x >> 6;                 // 0..3: row within block
        int t = threadIdx.x & 63;                 // float4 index within row
        int k = (blockIdx.x - 2048) * 4 + g;      // 0..K_PAD-1
        float4 v = make_float4(0.f, 0.f, 0.f, 0.f);
        if (k < K_SUB) v = ((const float4*)(cb + (size_t)rnd[k] * D_DIM))[t];
        __half h[4] = {__float2half_rn(v.x), __float2half_rn(v.y),
                       __float2half_rn(v.z), __float2half_rn(v.w)};
        *(uint2*)(g_ch + (size_t)k * D_DIM + t * 4) = *(uint2*)h;
        float lx = v.x - __half2float(h[0]), ly = v.y - __half2float(h[1]);
        float lz = v.z - __half2float(h[2]), lw = v.w - __half2float(h[3]);
        float s2 = v.x*v.x + v.y*v.y + v.z*v.z + v.w*v.w;
        float sl = lx*lx + ly*ly + lz*lz + lw*lw;
        #pragma unroll
        for (int o = 16; o; o >>= 1) {
            s2 += __shfl_down_sync(0xffffffffu, s2, o);
            sl += __shfl_down_sync(0xffffffffu, sl, o);
        }
        if ((t & 31) == 0) { s2w[g][t >> 5] = s2; slw[g][t >> 5] = sl; }
        __syncthreads();
        if (t == 0) {
            float c2 = s2w[g][0] + s2w[g][1];
            float cl2 = slw[g][0] + slw[g][1];
            g_c2[k] = (k < K_SUB) ? c2 : 3.0e38f;
            if (k < K_SUB) {
                atomicMax(&g_mc,  __float_as_uint(sqrtf(c2)));
                atomicMax(&g_mcl, __float_as_uint(sqrtf(cl2)));
            }
        }
    }
}

// --- kernel 2: fp16 HMMA GEMM -> per-tile exact min + per-4-group fp16 min ---
// (R14 config: grid 128x29, 256 threads, 2 CTAs/SM, 3-stage ring)
#define CHUNK_H 64
#define A_CH (128 * 128)              // 16 KB
#define B_CH (128 * 128)              // 16 KB
#define STAGE (A_CH + B_CH)           // 32 KB
#define DYN_SMEM (3 * STAGE + 1024)

__global__ void __launch_bounds__(256, 2) k_tc(void) {
    extern __shared__ __align__(16) unsigned char dynraw[];
    char* sb = (char*)(((uintptr_t)dynraw + 1023) & ~(uintptr_t)1023);
    const uint32_t s0 = smem_u32(sb);

    __shared__ float c2s[128];
    __shared__ float sd[128][4];
    __shared__ __align__(16) __half sd2[128][32];   // per-row 32 group mins (8 KB)

    const int tid = threadIdx.x;
    const int wid = tid >> 5, lane = tid & 31;
    const int wm = wid & 1, wn = wid >> 1;
    const int lr = lane & 7, lg = lane >> 3;
    const int tokBase = blockIdx.x * 128;
    const int nBase   = blockIdx.y * 128;

    if (tid < 128) c2s[tid] = g_c2[nBase + tid];

    const __half* Ag = g_xh + (size_t)tokBase * D_DIM;
    const __half* Bg = g_ch + (size_t)nBase * D_DIM;

    float acc[4][4][4];
    #pragma unroll
    for (int a = 0; a < 4; a++)
        #pragma unroll
        for (int b = 0; b < 4; b++)
            #pragma unroll
            for (int e = 0; e < 4; e++) acc[a][b][e] = 0.f;

    int arow[4], brow[2];
    #pragma unroll
    for (int mf = 0; mf < 4; mf++) arow[mf] = wm * 64 + mf * 16 + lr + ((lg & 1) << 3);
    #pragma unroll
    for (int nb = 0; nb < 2; nb++) brow[nb] = wn * 32 + nb * 16 + lr + ((lg >> 1) << 3);
    const int acol = lg >> 1, bcol = lg & 1;

    auto issue = [&](int ch) {
        const uint32_t st = s0 + (ch % 3) * STAGE;
        #pragma unroll
        for (int q = 0; q < 4; q++) {
            int idx = q * 256 + tid;
            int row = idx >> 3, c = idx & 7;
            cpa16(st + row * 128 + ((c ^ (row & 7)) << 4),
                  Ag + (size_t)row * D_DIM + ch * CHUNK_H + c * 8);
        }
        #pragma unroll
        for (int q = 0; q < 4; q++) {
            int idx = q * 256 + tid;
            int row = idx >> 3, c = idx & 7;
            cpa16(st + A_CH + row * 128 + ((c ^ (row & 7)) << 4),
                  Bg + (size_t)row * D_DIM + ch * CHUNK_H + c * 8);
        }
        CP_COMMIT();
    };

    issue(0);
    issue(1);
    #pragma unroll 1
    for (int ch = 0; ch < 4; ++ch) {
        if (ch < 3) { CP_WAIT(1); } else { CP_WAIT(0); }
        __syncthreads();
        if (ch + 2 < 4) issue(ch + 2);

        const uint32_t sA = s0 + (ch % 3) * STAGE;
        const uint32_t sB = sA + A_CH;
        #pragma unroll
        for (int ks = 0; ks < 4; ++ks) {
            uint32_t af[4][4], bf[2][4];
            #pragma unroll
            for (int mf = 0; mf < 4; mf++) {
                int r = arow[mf], c16 = ks * 2 + acol;
                ldsm4(af[mf], sA + r * 128 + ((c16 ^ (r & 7)) << 4));
            }
            #pragma unroll
            for (int nb = 0; nb < 2; nb++) {
                int r = brow[nb], c16 = ks * 2 + bcol;
                ldsm4(bf[nb], sB + r * 128 + ((c16 ^ (r & 7)) << 4));
            }
            #pragma unroll
            for (int mf = 0; mf < 4; mf++)
                #pragma unroll
                for (int nf = 0; nf < 4; nf++)
                    mma16816(acc[mf][nf], af[mf], bf[nf >> 1][(nf & 1) * 2],
                             bf[nf >> 1][(nf & 1) * 2 + 1]);
        }
    }

    // epilogue: d_hh = ||c||^2 - 2*dot; group-of-4 mins (fp16 rd) + tile min
    #pragma unroll
    for (int mf = 0; mf < 4; mf++) {
        #pragma unroll
        for (int h = 0; h < 2; h++) {
            int rowL = wm * 64 + mf * 16 + (lane >> 2) + h * 8;
            float best = 3.4e38f;
            #pragma unroll
            for (int nf = 0; nf < 4; nf++) {
                int colL = wn * 32 + nf * 8 + (lane & 3) * 2;
                float d0 = c2s[colL]     - 2.0f * acc[mf][nf][h * 2];
                float d1 = c2s[colL + 1] - 2.0f * acc[mf][nf][h * 2 + 1];
                float m2 = fminf(d0, d1);
                float mq = fminf(m2, __shfl_xor_sync(0xffffffffu, m2, 1));
                if (((lane & 3) & 1) == 0)
                    sd2[rowL][wn * 8 + nf * 2 + ((lane & 3) >> 1)] = __float2half_rd(mq);
                best = fminf(best, fminf(mq, __shfl_xor_sync(0xffffffffu, mq, 2)));
            }
            if ((lane & 3) == 0) sd[rowL][wn] = best;
        }
    }
    __syncthreads();

    if (tid < 128) {
        float tmin = fminf(fminf(sd[tid][0], sd[tid][1]),
                           fminf(sd[tid][2], sd[tid][3]));
        g_tmin[(tokBase + tid) * 32 + blockIdx.y] = tmin;
        const uint4* s = (const uint4*)&sd2[tid][0];             // 64 B row
        uint4* d = (uint4*)(g_gmin + (size_t)(tokBase + tid) * NGRP + blockIdx.y * 32);
        d[0] = s[0]; d[1] = s[1]; d[2] = s[2]; d[3] = s[3];
    }
}

// ------- kernel 3: rescue + exact argmin + fused gather + loss partial -------
__global__ void k_rescue(const float* __restrict__ x, const float* __restrict__ cb,
                         const int* __restrict__ rnd, float* __restrict__ out) {
    int wid = threadIdx.x >> 5, lane = threadIdx.x & 31;
    int tok = blockIdx.x * 8 + wid;

    float tm = (lane < N_YT) ? g_tmin[tok * 32 + lane] : 3.4e38f;
    float dmin = tm;
    #pragma unroll
    for (int o = 16; o; o >>= 1)
        dmin = fminf(dmin, __shfl_xor_sync(0xffffffffu, dmin, o));

    float MCL = __uint_as_float(g_mcl), MC = __uint_as_float(g_mc);
    float B = 2.0f * (g_nxh[tok] * MCL + g_nxl[tok] * MC);
    float thr = dmin + 2.0f * B + 0.01f;      // rd-rounded group mins: no fp16 slack
    unsigned tmask = __ballot_sync(0xffffffffu, tm <= thr);

    const float* xr = x + (size_t)tok * D_DIM + lane * 8;
    float4 xa = ((const float4*)xr)[0];
    float4 xb = ((const float4*)xr)[1];

    float best = 3.4e38f; int bi = 0x7fffffff;
    auto exact = [&](int kk) {
        const float* cr = cb + (size_t)rnd[kk] * D_DIM + lane * 8;
        float4 ca = ((const float4*)cr)[0];
        float4 cv = ((const float4*)cr)[1];
        float p = xa.x*ca.x + xa.y*ca.y + xa.z*ca.z + xa.w*ca.w
                + xb.x*cv.x + xb.y*cv.y + xb.z*cv.z + xb.w*cv.w;
        #pragma unroll
        for (int o = 16; o; o >>= 1) p += __shfl_xor_sync(0xffffffffu, p, o);
        float dex = g_c2[kk] - 2.0f * p;
        if (dex < best || (dex == best && kk < bi)) { best = dex; bi = kk; }
    };

    const __half* grow = g_gmin + (size_t)tok * NGRP;
    while (tmask) {
        int t = __ffs(tmask) - 1; tmask &= tmask - 1;
        float gm = __half2float(grow[t * 32 + lane]);   // 32 group mins, 1/lane
        unsigned gmask = __ballot_sync(0xffffffffu, gm <= thr);
        while (gmask) {
            int g = __ffs(gmask) - 1; gmask &= gmask - 1;
            int kb = t * 128 + g * 4;
            exact(kb); exact(kb + 1); exact(kb + 2); exact(kb + 3);
        }
    }

    // fused gather + per-token loss
    int ci = rnd[bi];
    const float4* crow = (const float4*)(cb + (size_t)ci * D_DIM);
    float4 c0 = crow[lane * 2], c1 = crow[lane * 2 + 1];
    float4* orow = (float4*)(out + (size_t)tok * D_DIM);
    orow[lane * 2] = c0; orow[lane * 2 + 1] = c1;
    float dx, s = 0.f;
    dx = c0.x - xa.x; s += dx * dx;  dx = c0.y - xa.y; s += dx * dx;
    dx = c0.z - xa.z; s += dx * dx;  dx = c0.w - xa.w; s += dx * dx;
    dx = c1.x - xb.x; s += dx * dx;  dx = c1.y - xb.y; s += dx * dx;
    dx = c1.z - xb.z; s += dx * dx;  dx = c1.w - xb.w; s += dx * dx;
    #pragma unroll
    for (int o = 16; o; o >>= 1) s += __shfl_xor_sync(0xffffffffu, s, o);
    if (lane == 0) {
        g_tokloss[tok] = s;
        out[OUT_IDX + tok] = (float)ci;
    }
}

// ---------------- kernel 4: deterministic loss reduce ----------------
__global__ void k_loss(float* __restrict__ out) {
    __shared__ float red[1024];
    int tid = threadIdx.x;
    float s = 0.f;
    for (int j = tid; j < N_TOK; j += 1024) s += g_tokloss[j];
    red[tid] = s;
    __syncthreads();
    for (int o = 512; o; o >>= 1) {
        if (tid < o) red[tid] += red[tid + o];
        __syncthreads();
    }
    if (tid == 0) out[OUT_LOSS] = red[0] / (float)OUT_TOKENS;
}

// ---------------- launch ----------------
extern "C" void kernel_launch(void* const* d_in, const int* in_sizes, int n_in,
                              void* d_out, int out_size) {
    const float* x   = (const float*)d_in[0];
    const float* cb  = (const float*)d_in[1];
    const int*   rnd = (const int*)d_in[2];
    float* out = (float*)d_out;

    static int smem_set = 0;
    if (!smem_set) {
        cudaFuncSetAttribute(k_tc, cudaFuncAttributeMaxDynamicSharedMemorySize, DYN_SMEM);
        smem_set = 1;
    }

    k_prep<<<2976, 256>>>(x, cb, rnd);
    k_tc<<<dim3(128, N_YT), 256, DYN_SMEM>>>();
    k_rescue<<<2048, 256>>>(x, cb, rnd, out);
    k_loss<<<1, 1024>>>(out);
}